// round 13
// baseline (speedup 1.0000x reference)
#include <cuda_runtime.h>

#define Nn 32
#define Cc 512
#define Hh 64
#define Ww 64
#define CBn 32          // bottleneck channels C/R
#define Sp (Hh*Ww)      // 4096 spatial per channel
#define EPSv 1e-5f
#define GRP 4           // 4 * 8MB = 32MB per group; 3 in flight = 96MB < 126MB L2
#define NSTREAMS 3      // 4 streams triggered a graph-upload leak (R9/R12); keep 3

// PDL device-side primitives (sm_90+)
__device__ __forceinline__ void pdl_wait() {
    asm volatile("griddepcontrol.wait;" ::: "memory");
}
__device__ __forceinline__ void pdl_trigger() {
    asm volatile("griddepcontrol.launch_dependents;" ::: "memory");
}

// Scratch (allocation-free rule: __device__ globals). Indexed by global n ->
// disjoint across concurrently-running groups.
__device__ float g_attn[Nn * Sp];      // logits -> attn (in place)
__device__ float g_ctx[Nn * Cc];       // pooled context
__device__ float g_v[Nn * CBn];        // post-LN/ReLU bottleneck vector

// ---------------------------------------------------------------------------
// K1: logits[n,h,w] = sum_c x[n,c,h,w] * wk_w[c] + wk_b
// block = (n,h) row; 512 threads = 16 w-float4 groups x 32 c-chunks of 16.
// 16 fully-unrolled independent loads/thread + 48 warps/SM -> 2x the MLP of
// the old 256-thread version (which measured only 3.2 TB/s).
// ---------------------------------------------------------------------------
__global__ void __launch_bounds__(512, 3)
k_logits(const float* __restrict__ x,
         const float* __restrict__ wk_w,
         const float* __restrict__ wk_b, int n0) {
    int n = n0 + (blockIdx.x >> 6);   // / Hh
    int h = blockIdx.x & 63;          // % Hh
    int tid = threadIdx.x;            // 0..511
    int wq = tid & 15;                // float4 index over w (w = wq*4)
    int cc = tid >> 4;                // c-chunk 0..31 (16 channels each)

    const float4* xp = (const float4*)(x + (((size_t)(n * Cc + cc * 16)) * Hh + h) * Ww) + wq;
    const size_t cstride4 = Sp / 4;   // float4 stride between channels = 1024

    float4 acc = make_float4(0.f, 0.f, 0.f, 0.f);
#pragma unroll
    for (int i = 0; i < 16; i++) {
        float wv = __ldg(&wk_w[cc * 16 + i]);
        float4 v = __ldg(xp + (size_t)i * cstride4);
        acc.x += v.x * wv; acc.y += v.y * wv;
        acc.z += v.z * wv; acc.w += v.w * wv;
    }

    __shared__ float sred[32][Ww];    // 8KB
    sred[cc][wq * 4 + 0] = acc.x;
    sred[cc][wq * 4 + 1] = acc.y;
    sred[cc][wq * 4 + 2] = acc.z;
    sred[cc][wq * 4 + 3] = acc.w;
    __syncthreads();

    if (tid < Ww) {
        float s = 0.f;
#pragma unroll
        for (int k = 0; k < 32; k++) s += sred[k][tid];
        g_attn[((size_t)n * Hh + h) * Ww + tid] = s + __ldg(&wk_b[0]);
    }
    __syncthreads();
    pdl_trigger();                    // logits row written -> softmax may go
}

// ---------------------------------------------------------------------------
// K2: softmax over H (axis=1) per (n, w), in place. block per n, 256 threads.
// ---------------------------------------------------------------------------
__global__ void k_softmax(int n0) {
    pdl_wait();
    int n = n0 + blockIdx.x;
    int tid = threadIdx.x;            // 0..255
    int w = tid & 63;
    int hq = tid >> 6;                // 0..3
    float* L = g_attn + (size_t)n * Sp;

    __shared__ float sp[4][Ww];       // partials
    __shared__ float sfin[Ww];        // combined max / inv-sum

    float vals[16];
    float m = -1e30f;
#pragma unroll
    for (int i = 0; i < 16; i++) {
        vals[i] = L[(hq * 16 + i) * Ww + w];
        m = fmaxf(m, vals[i]);
    }
    sp[hq][w] = m;
    __syncthreads();
    if (hq == 0) sfin[w] = fmaxf(fmaxf(sp[0][w], sp[1][w]), fmaxf(sp[2][w], sp[3][w]));
    __syncthreads();
    float fm = sfin[w];

    float sum = 0.f;
#pragma unroll
    for (int i = 0; i < 16; i++) {
        vals[i] = __expf(vals[i] - fm);
        sum += vals[i];
    }
    sp[hq][w] = sum;
    __syncthreads();
    if (hq == 0) sfin[w] = 1.f / (sp[0][w] + sp[1][w] + sp[2][w] + sp[3][w]);
    __syncthreads();
    float inv = sfin[w];
#pragma unroll
    for (int i = 0; i < 16; i++) L[(hq * 16 + i) * Ww + w] = vals[i] * inv;
    __syncthreads();
    pdl_trigger();                    // attn ready -> ctx may consume
}

// ---------------------------------------------------------------------------
// K3: ctx[n,c] = sum_{h,w} x[n,c,h,w] * attn[n,h,w]   (x hits L2)
// PDL: issues its full x-tile load BEFORE the wait (overlaps softmax).
// ---------------------------------------------------------------------------
__global__ void k_ctx(const float* __restrict__ x, int n0) {
    int n = n0 + (blockIdx.x >> 9);   // / Cc
    int c = blockIdx.x & 511;         // % Cc
    int tid = threadIdx.x;            // 0..127

    // Prefetch x tile (independent of softmax)
    const float4* xp = (const float4*)(x + ((size_t)n * Cc + c) * Sp);
    float4 xv[8];
#pragma unroll
    for (int i = 0; i < 8; i++) xv[i] = __ldg(xp + tid + i * 128);

    pdl_wait();                       // attn now valid

    const float4* ap = (const float4*)(g_attn + (size_t)n * Sp);
    float acc = 0.f;
#pragma unroll
    for (int i = 0; i < 8; i++) {
        float4 av = __ldg(ap + tid + i * 128);
        acc += xv[i].x * av.x + xv[i].y * av.y + xv[i].z * av.z + xv[i].w * av.w;
    }

    __shared__ float s[128];
    s[tid] = acc;
    __syncthreads();
    if (tid < 64) s[tid] += s[tid + 64];
    __syncthreads();
    if (tid < 32) {
        float v = s[tid] + s[tid + 32];
#pragma unroll
        for (int o = 16; o; o >>= 1) v += __shfl_xor_sync(0xffffffffu, v, o);
        if (tid == 0) g_ctx[(size_t)n * Cc + c] = v;
    }
    __syncthreads();
    pdl_trigger();                    // this block's ctx written
}

// ---------------------------------------------------------------------------
// K4: bottleneck head: v = ReLU(LN(ctx @ wv1^T)). grid=GRP, 1024 threads.
// PDL: prefetches wv1 into registers BEFORE the wait.
// ---------------------------------------------------------------------------
__global__ void __launch_bounds__(1024, 1)
k_bneck(const float* __restrict__ wv1,
        const float* __restrict__ ln_g,
        const float* __restrict__ ln_b, int n0) {
    int n = n0 + blockIdx.x;
    int tid = threadIdx.x;            // 0..1023
    int j = tid >> 5;                 // warp = bottleneck channel 0..31
    int lane = tid & 31;

    // Prefetch weights (independent of ctx)
    const float4* w1 = (const float4*)(wv1 + (size_t)j * Cc);
    float4 wv[4];
#pragma unroll
    for (int k = 0; k < 4; k++) wv[k] = __ldg(w1 + lane + k * 32);

    pdl_wait();                       // g_ctx now valid

    __shared__ float4 sctx4[Cc / 4];  // 128 float4
    __shared__ float sv[CBn];
    if (tid < Cc / 4)
        sctx4[tid] = __ldg((const float4*)(g_ctx + (size_t)n * Cc) + tid);
    __syncthreads();

    float acc = 0.f;
#pragma unroll
    for (int k = 0; k < 4; k++) {
        float4 cx = sctx4[lane + k * 32];
        acc += cx.x * wv[k].x + cx.y * wv[k].y + cx.z * wv[k].z + cx.w * wv[k].w;
    }
#pragma unroll
    for (int o = 16; o; o >>= 1) acc += __shfl_xor_sync(0xffffffffu, acc, o);
    if (lane == 0) sv[j] = acc;
    __syncthreads();

    if (tid < 32) {
        float v = sv[lane];
        float mu = v;
#pragma unroll
        for (int o = 16; o; o >>= 1) mu += __shfl_xor_sync(0xffffffffu, mu, o);
        mu *= (1.f / 32.f);
        float d = v - mu;
        float var = d * d;
#pragma unroll
        for (int o = 16; o; o >>= 1) var += __shfl_xor_sync(0xffffffffu, var, o);
        var *= (1.f / 32.f);
        v = d * rsqrtf(var + EPSv) * __ldg(&ln_g[lane]) + __ldg(&ln_b[lane]);
        g_v[(size_t)n * CBn + lane] = fmaxf(v, 0.f);
    }
    __syncthreads();
    pdl_trigger();                    // v ready -> add may consume
}

// ---------------------------------------------------------------------------
// K5: out[n,c,:] = x[n,c,:] + dot(v[n,:], wv2[c,:]).  Block per (n,c).
// PDL: prefetches x + wv2 BEFORE the wait (hides bneck); triggers EARLY,
// right after delta, so the next chain's logits overlaps our streaming store.
// ---------------------------------------------------------------------------
__global__ void __launch_bounds__(256)
k_add(const float* __restrict__ x, float* __restrict__ out,
      const float* __restrict__ wv2, int n0) {
    int n = n0 + (blockIdx.x >> 9);   // / Cc
    int c = blockIdx.x & 511;         // % Cc
    int tid = threadIdx.x;            // 0..255

    // Prefetch x (independent of bneck)
    const float4* xp = (const float4*)(x + ((size_t)n * Cc + c) * Sp);
    float4 xv[4];
#pragma unroll
    for (int it = 0; it < 4; it++) xv[it] = __ldg(xp + it * 256 + tid);
    // Prefetch wv2 row (independent of bneck)
    const float4* w2 = (const float4*)(wv2 + (size_t)c * CBn);
    float4 w2v[8];
#pragma unroll
    for (int q = 0; q < 8; q++) w2v[q] = __ldg(w2 + q);

    pdl_wait();                       // g_v now valid

    const float4* vp = (const float4*)(g_v + (size_t)n * CBn);
    float d = 0.f;
#pragma unroll
    for (int q = 0; q < 8; q++) {
        float4 vv = __ldg(vp + q);
        d += vv.x * w2v[q].x + vv.y * w2v[q].y + vv.z * w2v[q].z + vv.w * w2v[q].w;
    }

    pdl_trigger();                    // EARLY: next chain's logits can launch
                                      // while we stream the residual add out.

    float4* op = (float4*)(out + ((size_t)n * Cc + c) * Sp);
#pragma unroll
    for (int it = 0; it < 4; it++) {
        int f = it * 256 + tid;       // 1024 float4 per channel
        op[f] = make_float4(xv[it].x + d, xv[it].y + d, xv[it].z + d, xv[it].w + d);
    }
}

// ---------------------------------------------------------------------------
// PDL launch helper
// ---------------------------------------------------------------------------
template <typename K, typename... Args>
static void launch_pdl(K kern, dim3 grid, dim3 block, cudaStream_t st, Args... args) {
    cudaLaunchConfig_t cfg = {};
    cfg.gridDim = grid;
    cfg.blockDim = block;
    cfg.dynamicSmemBytes = 0;
    cfg.stream = st;
    cudaLaunchAttribute attr[1];
    attr[0].id = cudaLaunchAttributeProgrammaticStreamSerialization;
    attr[0].val.programmaticStreamSerializationAllowed = 1;
    cfg.attrs = attr;
    cfg.numAttrs = 1;
    cudaLaunchKernelEx(&cfg, kern, args...);
}

// ---------------------------------------------------------------------------
extern "C" void kernel_launch(void* const* d_in, const int* in_sizes, int n_in,
                              void* d_out, int out_size) {
    const float* x    = (const float*)d_in[0];
    const float* wk_w = (const float*)d_in[1];
    const float* wk_b = (const float*)d_in[2];
    const float* wv1  = (const float*)d_in[3];
    const float* ln_g = (const float*)d_in[4];
    const float* ln_b = (const float*)d_in[5];
    const float* wv2  = (const float*)d_in[6];
    float* out = (float*)d_out;

    static cudaStream_t streams[NSTREAMS];
    static cudaEvent_t ev_root, ev_done[NSTREAMS];
    static bool res_init = false;
    if (!res_init) {
        for (int i = 0; i < NSTREAMS; i++) {
            cudaStreamCreateWithFlags(&streams[i], cudaStreamNonBlocking);
            cudaEventCreateWithFlags(&ev_done[i], cudaEventDisableTiming);
        }
        cudaEventCreateWithFlags(&ev_root, cudaEventDisableTiming);
        res_init = true;
    }

    // Fork the capture stream into side streams.
    cudaEventRecord(ev_root, 0);
    for (int i = 0; i < NSTREAMS; i++)
        cudaStreamWaitEvent(streams[i], ev_root, 0);

    for (int g = 0; g < Nn / GRP; g++) {
        int n0 = g * GRP;
        cudaStream_t st = streams[g % NSTREAMS];
        launch_pdl(k_logits, dim3(GRP * Hh), dim3(512), st, x, wk_w, wk_b, n0);
        launch_pdl(k_softmax, dim3(GRP), dim3(256), st, n0);
        launch_pdl(k_ctx, dim3(GRP * Cc), dim3(128), st, x, n0);
        launch_pdl(k_bneck, dim3(GRP), dim3(1024), st, wv1, ln_g, ln_b, n0);
        launch_pdl(k_add, dim3(GRP * Cc), dim3(256), st, x, out, wv2, n0);
    }

    for (int i = 0; i < NSTREAMS; i++) {
        cudaEventRecord(ev_done[i], streams[i]);
        cudaStreamWaitEvent(0, ev_done[i], 0);
    }
}

// round 14
// speedup vs baseline: 1.0197x; 1.0197x over previous
#include <cuda_runtime.h>

#define Nn 32
#define Cc 512
#define Hh 64
#define Ww 64
#define CBn 32          // bottleneck channels C/R
#define Sp (Hh*Ww)      // 4096 spatial per channel
#define EPSv 1e-5f
#define GRP 4           // 4 * 8MB = 32MB per group; 3 in flight = 96MB < 126MB L2
#define NSTREAMS 3      // 4 streams triggered a graph-upload leak (R9/R12); keep 3

// PDL device-side primitives (sm_90+)
__device__ __forceinline__ void pdl_wait() {
    asm volatile("griddepcontrol.wait;" ::: "memory");
}
__device__ __forceinline__ void pdl_trigger() {
    asm volatile("griddepcontrol.launch_dependents;" ::: "memory");
}

// Scratch (allocation-free rule: __device__ globals). Indexed by global n ->
// disjoint across concurrently-running groups.
__device__ float g_attn[Nn * Sp];      // logits -> attn (in place)
__device__ float g_ctx[Nn * Cc];       // pooled context
__device__ float g_v[Nn * CBn];        // post-LN/ReLU bottleneck vector

// ---------------------------------------------------------------------------
// K1: logits[n,h,w] = sum_c x[n,c,h,w] * wk_w[c] + wk_b
// block = (n,h) row; 256 threads = 16 w-float4 groups x 16 c-chunks of 32.
// (R11 shape — the 512-thread variant measured neutral-negative.)
// ---------------------------------------------------------------------------
__global__ void __launch_bounds__(256, 6)
k_logits(const float* __restrict__ x,
         const float* __restrict__ wk_w,
         const float* __restrict__ wk_b, int n0) {
    int n = n0 + (blockIdx.x >> 6);   // / Hh
    int h = blockIdx.x & 63;          // % Hh
    int tid = threadIdx.x;            // 0..255
    int wq = tid & 15;                // float4 index over w (w = wq*4)
    int cc = tid >> 4;                // c-chunk 0..15 (32 channels each)

    const float4* xp = (const float4*)(x + (((size_t)(n * Cc + cc * 32)) * Hh + h) * Ww) + wq;
    const size_t cstride4 = Sp / 4;   // float4 stride between channels = 1024

    float4 acc = make_float4(0.f, 0.f, 0.f, 0.f);
#pragma unroll 8
    for (int i = 0; i < 32; i++) {
        float wv = __ldg(&wk_w[cc * 32 + i]);
        float4 v = __ldg(xp + (size_t)i * cstride4);
        acc.x += v.x * wv; acc.y += v.y * wv;
        acc.z += v.z * wv; acc.w += v.w * wv;
    }

    __shared__ float sred[16][Ww];
    sred[cc][wq * 4 + 0] = acc.x;
    sred[cc][wq * 4 + 1] = acc.y;
    sred[cc][wq * 4 + 2] = acc.z;
    sred[cc][wq * 4 + 3] = acc.w;
    __syncthreads();

    if (tid < Ww) {
        float s = 0.f;
#pragma unroll
        for (int k = 0; k < 16; k++) s += sred[k][tid];
        g_attn[((size_t)n * Hh + h) * Ww + tid] = s + __ldg(&wk_b[0]);
    }
    __syncthreads();
    pdl_trigger();                    // logits row written -> softmax may go
}

// ---------------------------------------------------------------------------
// K2: softmax over H (axis=1) per (n, w), in place. block per n, 256 threads.
// ---------------------------------------------------------------------------
__global__ void k_softmax(int n0) {
    pdl_wait();
    int n = n0 + blockIdx.x;
    int tid = threadIdx.x;            // 0..255
    int w = tid & 63;
    int hq = tid >> 6;                // 0..3
    float* L = g_attn + (size_t)n * Sp;

    __shared__ float sp[4][Ww];       // partials
    __shared__ float sfin[Ww];        // combined max / inv-sum

    float vals[16];
    float m = -1e30f;
#pragma unroll
    for (int i = 0; i < 16; i++) {
        vals[i] = L[(hq * 16 + i) * Ww + w];
        m = fmaxf(m, vals[i]);
    }
    sp[hq][w] = m;
    __syncthreads();
    if (hq == 0) sfin[w] = fmaxf(fmaxf(sp[0][w], sp[1][w]), fmaxf(sp[2][w], sp[3][w]));
    __syncthreads();
    float fm = sfin[w];

    float sum = 0.f;
#pragma unroll
    for (int i = 0; i < 16; i++) {
        vals[i] = __expf(vals[i] - fm);
        sum += vals[i];
    }
    sp[hq][w] = sum;
    __syncthreads();
    if (hq == 0) sfin[w] = 1.f / (sp[0][w] + sp[1][w] + sp[2][w] + sp[3][w]);
    __syncthreads();
    float inv = sfin[w];
#pragma unroll
    for (int i = 0; i < 16; i++) L[(hq * 16 + i) * Ww + w] = vals[i] * inv;
    __syncthreads();
    pdl_trigger();                    // attn ready -> ctx may consume
}

// ---------------------------------------------------------------------------
// K3: ctx for FOUR channels per block. Block = (n, cg) with cg in [0,128);
// channels c = cg*4 + sub, sub = tid/64. The 16KB attn tile is staged in smem
// ONCE per block -> attn L2 traffic drops 4x (256MB -> 64MB chip-wide).
// 2 warps (64 threads) per channel; each thread covers 16 float4 of x.
// PDL: prefetches half its x slice before the wait (hides softmax).
// ---------------------------------------------------------------------------
__global__ void __launch_bounds__(256)
k_ctx(const float* __restrict__ x, int n0) {
    int n = n0 + (blockIdx.x >> 7);   // / 128
    int cg = blockIdx.x & 127;        // 4-channel group
    int tid = threadIdx.x;            // 0..255
    int sub = tid >> 6;               // channel-within-group 0..3
    int st  = tid & 63;               // thread-within-channel 0..63
    int c = cg * 4 + sub;

    const float4* xp = (const float4*)(x + ((size_t)n * Cc + c) * Sp);

    // Prefetch first half of this thread's x slice (independent of softmax)
    float4 xv[8];
#pragma unroll
    for (int i = 0; i < 8; i++) xv[i] = __ldg(xp + st + i * 64);

    pdl_wait();                       // attn now valid

    // Stage attn tile in smem (1024 float4)
    __shared__ float4 sattn[Sp / 4];
    const float4* ap = (const float4*)(g_attn + (size_t)n * Sp);
#pragma unroll
    for (int i = 0; i < 4; i++) sattn[tid + i * 256] = __ldg(ap + tid + i * 256);
    __syncthreads();

    float acc = 0.f;
#pragma unroll
    for (int i = 0; i < 8; i++) {
        float4 av = sattn[st + i * 64];
        acc += xv[i].x * av.x + xv[i].y * av.y + xv[i].z * av.z + xv[i].w * av.w;
    }
#pragma unroll
    for (int i = 8; i < 16; i++) {
        float4 xw = __ldg(xp + st + i * 64);
        float4 av = sattn[st + i * 64];
        acc += xw.x * av.x + xw.y * av.y + xw.z * av.z + xw.w * av.w;
    }

    // Reduce 64 threads (2 warps) per channel
#pragma unroll
    for (int o = 16; o; o >>= 1) acc += __shfl_xor_sync(0xffffffffu, acc, o);
    __shared__ float spart[8];        // one per warp
    if ((tid & 31) == 0) spart[tid >> 5] = acc;
    __syncthreads();
    if (tid < 4)
        g_ctx[(size_t)n * Cc + cg * 4 + tid] = spart[2 * tid] + spart[2 * tid + 1];
    __syncthreads();
    pdl_trigger();                    // this block's ctx written
}

// ---------------------------------------------------------------------------
// K4: bottleneck head: v = ReLU(LN(ctx @ wv1^T)). grid=GRP, 1024 threads.
// PDL: prefetches wv1 into registers BEFORE the wait.
// ---------------------------------------------------------------------------
__global__ void __launch_bounds__(1024, 1)
k_bneck(const float* __restrict__ wv1,
        const float* __restrict__ ln_g,
        const float* __restrict__ ln_b, int n0) {
    int n = n0 + blockIdx.x;
    int tid = threadIdx.x;            // 0..1023
    int j = tid >> 5;                 // warp = bottleneck channel 0..31
    int lane = tid & 31;

    // Prefetch weights (independent of ctx)
    const float4* w1 = (const float4*)(wv1 + (size_t)j * Cc);
    float4 wv[4];
#pragma unroll
    for (int k = 0; k < 4; k++) wv[k] = __ldg(w1 + lane + k * 32);

    pdl_wait();                       // g_ctx now valid

    __shared__ float4 sctx4[Cc / 4];  // 128 float4
    __shared__ float sv[CBn];
    if (tid < Cc / 4)
        sctx4[tid] = __ldg((const float4*)(g_ctx + (size_t)n * Cc) + tid);
    __syncthreads();

    float acc = 0.f;
#pragma unroll
    for (int k = 0; k < 4; k++) {
        float4 cx = sctx4[lane + k * 32];
        acc += cx.x * wv[k].x + cx.y * wv[k].y + cx.z * wv[k].z + cx.w * wv[k].w;
    }
#pragma unroll
    for (int o = 16; o; o >>= 1) acc += __shfl_xor_sync(0xffffffffu, acc, o);
    if (lane == 0) sv[j] = acc;
    __syncthreads();

    if (tid < 32) {
        float v = sv[lane];
        float mu = v;
#pragma unroll
        for (int o = 16; o; o >>= 1) mu += __shfl_xor_sync(0xffffffffu, mu, o);
        mu *= (1.f / 32.f);
        float d = v - mu;
        float var = d * d;
#pragma unroll
        for (int o = 16; o; o >>= 1) var += __shfl_xor_sync(0xffffffffu, var, o);
        var *= (1.f / 32.f);
        v = d * rsqrtf(var + EPSv) * __ldg(&ln_g[lane]) + __ldg(&ln_b[lane]);
        g_v[(size_t)n * CBn + lane] = fmaxf(v, 0.f);
    }
    __syncthreads();
    pdl_trigger();                    // v ready -> add may consume
}

// ---------------------------------------------------------------------------
// K5: out[n,c,:] = x[n,c,:] + dot(v[n,:], wv2[c,:]).  Block per (n,c).
// PDL: prefetches x + wv2 BEFORE the wait (hides bneck); triggers EARLY,
// right after delta, so the next chain's logits overlaps our streaming store.
// ---------------------------------------------------------------------------
__global__ void __launch_bounds__(256)
k_add(const float* __restrict__ x, float* __restrict__ out,
      const float* __restrict__ wv2, int n0) {
    int n = n0 + (blockIdx.x >> 9);   // / Cc
    int c = blockIdx.x & 511;         // % Cc
    int tid = threadIdx.x;            // 0..255

    // Prefetch x (independent of bneck)
    const float4* xp = (const float4*)(x + ((size_t)n * Cc + c) * Sp);
    float4 xv[4];
#pragma unroll
    for (int it = 0; it < 4; it++) xv[it] = __ldg(xp + it * 256 + tid);
    // Prefetch wv2 row (independent of bneck)
    const float4* w2 = (const float4*)(wv2 + (size_t)c * CBn);
    float4 w2v[8];
#pragma unroll
    for (int q = 0; q < 8; q++) w2v[q] = __ldg(w2 + q);

    pdl_wait();                       // g_v now valid

    const float4* vp = (const float4*)(g_v + (size_t)n * CBn);
    float d = 0.f;
#pragma unroll
    for (int q = 0; q < 8; q++) {
        float4 vv = __ldg(vp + q);
        d += vv.x * w2v[q].x + vv.y * w2v[q].y + vv.z * w2v[q].z + vv.w * w2v[q].w;
    }

    pdl_trigger();                    // EARLY: next chain's logits can launch
                                      // while we stream the residual add out.

    float4* op = (float4*)(out + ((size_t)n * Cc + c) * Sp);
#pragma unroll
    for (int it = 0; it < 4; it++) {
        int f = it * 256 + tid;       // 1024 float4 per channel
        op[f] = make_float4(xv[it].x + d, xv[it].y + d, xv[it].z + d, xv[it].w + d);
    }
}

// ---------------------------------------------------------------------------
// PDL launch helper
// ---------------------------------------------------------------------------
template <typename K, typename... Args>
static void launch_pdl(K kern, dim3 grid, dim3 block, cudaStream_t st, Args... args) {
    cudaLaunchConfig_t cfg = {};
    cfg.gridDim = grid;
    cfg.blockDim = block;
    cfg.dynamicSmemBytes = 0;
    cfg.stream = st;
    cudaLaunchAttribute attr[1];
    attr[0].id = cudaLaunchAttributeProgrammaticStreamSerialization;
    attr[0].val.programmaticStreamSerializationAllowed = 1;
    cfg.attrs = attr;
    cfg.numAttrs = 1;
    cudaLaunchKernelEx(&cfg, kern, args...);
}

// ---------------------------------------------------------------------------
extern "C" void kernel_launch(void* const* d_in, const int* in_sizes, int n_in,
                              void* d_out, int out_size) {
    const float* x    = (const float*)d_in[0];
    const float* wk_w = (const float*)d_in[1];
    const float* wk_b = (const float*)d_in[2];
    const float* wv1  = (const float*)d_in[3];
    const float* ln_g = (const float*)d_in[4];
    const float* ln_b = (const float*)d_in[5];
    const float* wv2  = (const float*)d_in[6];
    float* out = (float*)d_out;

    static cudaStream_t streams[NSTREAMS];
    static cudaEvent_t ev_root, ev_done[NSTREAMS];
    static bool res_init = false;
    if (!res_init) {
        for (int i = 0; i < NSTREAMS; i++) {
            cudaStreamCreateWithFlags(&streams[i], cudaStreamNonBlocking);
            cudaEventCreateWithFlags(&ev_done[i], cudaEventDisableTiming);
        }
        cudaEventCreateWithFlags(&ev_root, cudaEventDisableTiming);
        res_init = true;
    }

    // Fork the capture stream into side streams.
    cudaEventRecord(ev_root, 0);
    for (int i = 0; i < NSTREAMS; i++)
        cudaStreamWaitEvent(streams[i], ev_root, 0);

    for (int g = 0; g < Nn / GRP; g++) {
        int n0 = g * GRP;
        cudaStream_t st = streams[g % NSTREAMS];
        launch_pdl(k_logits, dim3(GRP * Hh), dim3(256), st, x, wk_w, wk_b, n0);
        launch_pdl(k_softmax, dim3(GRP), dim3(256), st, n0);
        launch_pdl(k_ctx, dim3(GRP * 128), dim3(256), st, x, n0);
        launch_pdl(k_bneck, dim3(GRP), dim3(1024), st, wv1, ln_g, ln_b, n0);
        launch_pdl(k_add, dim3(GRP * Cc), dim3(256), st, x, out, wv2, n0);
    }

    for (int i = 0; i < NSTREAMS; i++) {
        cudaEventRecord(ev_done[i], streams[i]);
        cudaStreamWaitEvent(0, ev_done[i], 0);
    }
}

// round 15
// speedup vs baseline: 1.0577x; 1.0372x over previous
#include <cuda_runtime.h>

#define Nn 32
#define Cc 512
#define Hh 64
#define Ww 64
#define CBn 32          // bottleneck channels C/R
#define Sp (Hh*Ww)      // 4096 spatial per channel
#define EPSv 1e-5f
#define GRP 4           // 4 * 8MB = 32MB per group; 3 in flight = 96MB < 126MB L2
#define NSTREAMS 3      // 4 streams triggered a graph-upload leak (R9/R12); keep 3

// PDL device-side primitives (sm_90+)
__device__ __forceinline__ void pdl_wait() {
    asm volatile("griddepcontrol.wait;" ::: "memory");
}
__device__ __forceinline__ void pdl_trigger() {
    asm volatile("griddepcontrol.launch_dependents;" ::: "memory");
}

// Scratch (allocation-free rule: __device__ globals). Indexed by global n ->
// disjoint across concurrently-running groups.
__device__ float g_attn[Nn * Sp];      // logits -> attn (in place)
__device__ float g_ctx[Nn * Cc];       // pooled context
__device__ float g_v[Nn * CBn];        // post-LN/ReLU bottleneck vector

// ---------------------------------------------------------------------------
// K1: logits[n,h,w] = sum_c x[n,c,h,w] * wk_w[c] + wk_b
// block = (n,h) row; 256 threads = 16 w-float4 groups x 16 c-chunks of 32.
// x loaded with default policy: we WANT it resident in L2 for ctx/add.
// ---------------------------------------------------------------------------
__global__ void __launch_bounds__(256, 6)
k_logits(const float* __restrict__ x,
         const float* __restrict__ wk_w,
         const float* __restrict__ wk_b, int n0) {
    int n = n0 + (blockIdx.x >> 6);   // / Hh
    int h = blockIdx.x & 63;          // % Hh
    int tid = threadIdx.x;            // 0..255
    int wq = tid & 15;                // float4 index over w (w = wq*4)
    int cc = tid >> 4;                // c-chunk 0..15 (32 channels each)

    const float4* xp = (const float4*)(x + (((size_t)(n * Cc + cc * 32)) * Hh + h) * Ww) + wq;
    const size_t cstride4 = Sp / 4;   // float4 stride between channels = 1024

    float4 acc = make_float4(0.f, 0.f, 0.f, 0.f);
#pragma unroll 8
    for (int i = 0; i < 32; i++) {
        float wv = __ldg(&wk_w[cc * 32 + i]);
        float4 v = __ldg(xp + (size_t)i * cstride4);
        acc.x += v.x * wv; acc.y += v.y * wv;
        acc.z += v.z * wv; acc.w += v.w * wv;
    }

    __shared__ float sred[16][Ww];
    sred[cc][wq * 4 + 0] = acc.x;
    sred[cc][wq * 4 + 1] = acc.y;
    sred[cc][wq * 4 + 2] = acc.z;
    sred[cc][wq * 4 + 3] = acc.w;
    __syncthreads();

    if (tid < Ww) {
        float s = 0.f;
#pragma unroll
        for (int k = 0; k < 16; k++) s += sred[k][tid];
        g_attn[((size_t)n * Hh + h) * Ww + tid] = s + __ldg(&wk_b[0]);
    }
    __syncthreads();
    pdl_trigger();                    // logits row written -> softmax may go
}

// ---------------------------------------------------------------------------
// K2: softmax over H (axis=1) per (n, w), in place. block per n, 256 threads.
// ---------------------------------------------------------------------------
__global__ void k_softmax(int n0) {
    pdl_wait();
    int n = n0 + blockIdx.x;
    int tid = threadIdx.x;            // 0..255
    int w = tid & 63;
    int hq = tid >> 6;                // 0..3
    float* L = g_attn + (size_t)n * Sp;

    __shared__ float sp[4][Ww];       // partials
    __shared__ float sfin[Ww];        // combined max / inv-sum

    float vals[16];
    float m = -1e30f;
#pragma unroll
    for (int i = 0; i < 16; i++) {
        vals[i] = L[(hq * 16 + i) * Ww + w];
        m = fmaxf(m, vals[i]);
    }
    sp[hq][w] = m;
    __syncthreads();
    if (hq == 0) sfin[w] = fmaxf(fmaxf(sp[0][w], sp[1][w]), fmaxf(sp[2][w], sp[3][w]));
    __syncthreads();
    float fm = sfin[w];

    float sum = 0.f;
#pragma unroll
    for (int i = 0; i < 16; i++) {
        vals[i] = __expf(vals[i] - fm);
        sum += vals[i];
    }
    sp[hq][w] = sum;
    __syncthreads();
    if (hq == 0) sfin[w] = 1.f / (sp[0][w] + sp[1][w] + sp[2][w] + sp[3][w]);
    __syncthreads();
    float inv = sfin[w];
#pragma unroll
    for (int i = 0; i < 16; i++) L[(hq * 16 + i) * Ww + w] = vals[i] * inv;
    __syncthreads();
    pdl_trigger();                    // attn ready -> ctx may consume
}

// ---------------------------------------------------------------------------
// K3: ctx for FOUR channels per block. Block = (n, cg) with cg in [0,128);
// channels c = cg*4 + sub, sub = tid/64. The 16KB attn tile is staged in smem
// ONCE per block -> attn L2 traffic 4x lower. 2 warps per channel.
// PDL: prefetches half its x slice before the wait (hides softmax).
// x reads use default policy (keep resident for k_add).
// ---------------------------------------------------------------------------
__global__ void __launch_bounds__(256)
k_ctx(const float* __restrict__ x, int n0) {
    int n = n0 + (blockIdx.x >> 7);   // / 128
    int cg = blockIdx.x & 127;        // 4-channel group
    int tid = threadIdx.x;            // 0..255
    int sub = tid >> 6;               // channel-within-group 0..3
    int st  = tid & 63;               // thread-within-channel 0..63
    int c = cg * 4 + sub;

    const float4* xp = (const float4*)(x + ((size_t)n * Cc + c) * Sp);

    // Prefetch first half of this thread's x slice (independent of softmax)
    float4 xv[8];
#pragma unroll
    for (int i = 0; i < 8; i++) xv[i] = __ldg(xp + st + i * 64);

    pdl_wait();                       // attn now valid

    // Stage attn tile in smem (1024 float4)
    __shared__ float4 sattn[Sp / 4];
    const float4* ap = (const float4*)(g_attn + (size_t)n * Sp);
#pragma unroll
    for (int i = 0; i < 4; i++) sattn[tid + i * 256] = __ldg(ap + tid + i * 256);
    __syncthreads();

    float acc = 0.f;
#pragma unroll
    for (int i = 0; i < 8; i++) {
        float4 av = sattn[st + i * 64];
        acc += xv[i].x * av.x + xv[i].y * av.y + xv[i].z * av.z + xv[i].w * av.w;
    }
#pragma unroll
    for (int i = 8; i < 16; i++) {
        float4 xw = __ldg(xp + st + i * 64);
        float4 av = sattn[st + i * 64];
        acc += xw.x * av.x + xw.y * av.y + xw.z * av.z + xw.w * av.w;
    }

    // Reduce 64 threads (2 warps) per channel
#pragma unroll
    for (int o = 16; o; o >>= 1) acc += __shfl_xor_sync(0xffffffffu, acc, o);
    __shared__ float spart[8];        // one per warp
    if ((tid & 31) == 0) spart[tid >> 5] = acc;
    __syncthreads();
    if (tid < 4)
        g_ctx[(size_t)n * Cc + cg * 4 + tid] = spart[2 * tid] + spart[2 * tid + 1];
    __syncthreads();
    pdl_trigger();                    // this block's ctx written
}

// ---------------------------------------------------------------------------
// K4: bottleneck head: v = ReLU(LN(ctx @ wv1^T)). grid=GRP, 1024 threads.
// PDL: prefetches wv1 into registers BEFORE the wait.
// ---------------------------------------------------------------------------
__global__ void __launch_bounds__(1024, 1)
k_bneck(const float* __restrict__ wv1,
        const float* __restrict__ ln_g,
        const float* __restrict__ ln_b, int n0) {
    int n = n0 + blockIdx.x;
    int tid = threadIdx.x;            // 0..1023
    int j = tid >> 5;                 // warp = bottleneck channel 0..31
    int lane = tid & 31;

    // Prefetch weights (independent of ctx)
    const float4* w1 = (const float4*)(wv1 + (size_t)j * Cc);
    float4 wv[4];
#pragma unroll
    for (int k = 0; k < 4; k++) wv[k] = __ldg(w1 + lane + k * 32);

    pdl_wait();                       // g_ctx now valid

    __shared__ float4 sctx4[Cc / 4];  // 128 float4
    __shared__ float sv[CBn];
    if (tid < Cc / 4)
        sctx4[tid] = __ldg((const float4*)(g_ctx + (size_t)n * Cc) + tid);
    __syncthreads();

    float acc = 0.f;
#pragma unroll
    for (int k = 0; k < 4; k++) {
        float4 cx = sctx4[lane + k * 32];
        acc += cx.x * wv[k].x + cx.y * wv[k].y + cx.z * wv[k].z + cx.w * wv[k].w;
    }
#pragma unroll
    for (int o = 16; o; o >>= 1) acc += __shfl_xor_sync(0xffffffffu, acc, o);
    if (lane == 0) sv[j] = acc;
    __syncthreads();

    if (tid < 32) {
        float v = sv[lane];
        float mu = v;
#pragma unroll
        for (int o = 16; o; o >>= 1) mu += __shfl_xor_sync(0xffffffffu, mu, o);
        mu *= (1.f / 32.f);
        float d = v - mu;
        float var = d * d;
#pragma unroll
        for (int o = 16; o; o >>= 1) var += __shfl_xor_sync(0xffffffffu, var, o);
        var *= (1.f / 32.f);
        v = d * rsqrtf(var + EPSv) * __ldg(&ln_g[lane]) + __ldg(&ln_b[lane]);
        g_v[(size_t)n * CBn + lane] = fmaxf(v, 0.f);
    }
    __syncthreads();
    pdl_trigger();                    // v ready -> add may consume
}

// ---------------------------------------------------------------------------
// K5: out[n,c,:] = x[n,c,:] + dot(v[n,:], wv2[c,:]).  Block per (n,c).
// CACHE POLICY is the point of this round:
//   - x loaded with __ldcs (last use, evict-first)
//   - out stored with __stcs (streaming, write-once) -> out lines do NOT
//     evict the next groups' x from L2. In-flight L2 demand drops from
//     192MB (thrash) to 96MB (fits).
// PDL: prefetches x + wv2 BEFORE the wait; triggers EARLY after delta.
// ---------------------------------------------------------------------------
__global__ void __launch_bounds__(256)
k_add(const float* __restrict__ x, float* __restrict__ out,
      const float* __restrict__ wv2, int n0) {
    int n = n0 + (blockIdx.x >> 9);   // / Cc
    int c = blockIdx.x & 511;         // % Cc
    int tid = threadIdx.x;            // 0..255

    // Prefetch x (independent of bneck); last-use streaming load
    const float4* xp = (const float4*)(x + ((size_t)n * Cc + c) * Sp);
    float4 xv[4];
#pragma unroll
    for (int it = 0; it < 4; it++) xv[it] = __ldcs(xp + it * 256 + tid);
    // Prefetch wv2 row (independent of bneck)
    const float4* w2 = (const float4*)(wv2 + (size_t)c * CBn);
    float4 w2v[8];
#pragma unroll
    for (int q = 0; q < 8; q++) w2v[q] = __ldg(w2 + q);

    pdl_wait();                       // g_v now valid

    const float4* vp = (const float4*)(g_v + (size_t)n * CBn);
    float d = 0.f;
#pragma unroll
    for (int q = 0; q < 8; q++) {
        float4 vv = __ldg(vp + q);
        d += vv.x * w2v[q].x + vv.y * w2v[q].y + vv.z * w2v[q].z + vv.w * w2v[q].w;
    }

    pdl_trigger();                    // EARLY: next chain's logits can launch
                                      // while we stream the residual add out.

    float4* op = (float4*)(out + ((size_t)n * Cc + c) * Sp);
#pragma unroll
    for (int it = 0; it < 4; it++) {
        int f = it * 256 + tid;       // 1024 float4 per channel
        __stcs(op + f, make_float4(xv[it].x + d, xv[it].y + d,
                                   xv[it].z + d, xv[it].w + d));
    }
}

// ---------------------------------------------------------------------------
// PDL launch helper
// ---------------------------------------------------------------------------
template <typename K, typename... Args>
static void launch_pdl(K kern, dim3 grid, dim3 block, cudaStream_t st, Args... args) {
    cudaLaunchConfig_t cfg = {};
    cfg.gridDim = grid;
    cfg.blockDim = block;
    cfg.dynamicSmemBytes = 0;
    cfg.stream = st;
    cudaLaunchAttribute attr[1];
    attr[0].id = cudaLaunchAttributeProgrammaticStreamSerialization;
    attr[0].val.programmaticStreamSerializationAllowed = 1;
    cfg.attrs = attr;
    cfg.numAttrs = 1;
    cudaLaunchKernelEx(&cfg, kern, args...);
}

// ---------------------------------------------------------------------------
extern "C" void kernel_launch(void* const* d_in, const int* in_sizes, int n_in,
                              void* d_out, int out_size) {
    const float* x    = (const float*)d_in[0];
    const float* wk_w = (const float*)d_in[1];
    const float* wk_b = (const float*)d_in[2];
    const float* wv1  = (const float*)d_in[3];
    const float* ln_g = (const float*)d_in[4];
    const float* ln_b = (const float*)d_in[5];
    const float* wv2  = (const float*)d_in[6];
    float* out = (float*)d_out;

    static cudaStream_t streams[NSTREAMS];
    static cudaEvent_t ev_root, ev_done[NSTREAMS];
    static bool res_init = false;
    if (!res_init) {
        for (int i = 0; i < NSTREAMS; i++) {
            cudaStreamCreateWithFlags(&streams[i], cudaStreamNonBlocking);
            cudaEventCreateWithFlags(&ev_done[i], cudaEventDisableTiming);
        }
        cudaEventCreateWithFlags(&ev_root, cudaEventDisableTiming);
        res_init = true;
    }

    // Fork the capture stream into side streams.
    cudaEventRecord(ev_root, 0);
    for (int i = 0; i < NSTREAMS; i++)
        cudaStreamWaitEvent(streams[i], ev_root, 0);

    for (int g = 0; g < Nn / GRP; g++) {
        int n0 = g * GRP;
        cudaStream_t st = streams[g % NSTREAMS];
        launch_pdl(k_logits, dim3(GRP * Hh), dim3(256), st, x, wk_w, wk_b, n0);
        launch_pdl(k_softmax, dim3(GRP), dim3(256), st, n0);
        launch_pdl(k_ctx, dim3(GRP * 128), dim3(256), st, x, n0);
        launch_pdl(k_bneck, dim3(GRP), dim3(1024), st, wv1, ln_g, ln_b, n0);
        launch_pdl(k_add, dim3(GRP * Cc), dim3(256), st, x, out, wv2, n0);
    }

    for (int i = 0; i < NSTREAMS; i++) {
        cudaEventRecord(ev_done[i], streams[i]);
        cudaStreamWaitEvent(0, ev_done[i], 0);
    }
}